// round 2
// baseline (speedup 1.0000x reference)
#include <cuda_runtime.h>

#define Bb 4
#define Nn 1280
#define NM 256
#define NSd 1024
#define Cc 768
#define Hh 12
#define Dd 64
#define MEMN 1280
#define LFULL 2560
#define KSEL_S 640
#define KSEL_M 128
#define NT 256
#define KTP 257   // padded key stride for transposed K tile

// ---------------- scratch (static device globals; no allocation) ----------------
__device__ float g_q[Bb*Hh*Nn*Dd];
__device__ float g_k[Bb*Hh*Nn*Dd];
__device__ float g_v[Bb*Hh*Nn*Dd];
__device__ float g_qkvlow[Bb*Nn*24];
__device__ float g_idvlow[Bb*NM*8];
__device__ float g_act[Bb*NM*Hh];
__device__ float g_idv[Bb*NM*Cc];
__device__ float g_xo[Bb*Nn*Cc];
__device__ float g_wplow[Bb*Nn*32];

// ---------------- helpers ----------------
__device__ __forceinline__ unsigned fkey(float f){
    unsigned b = __float_as_uint(f);
    return (b & 0x80000000u) ? ~b : (b | 0x80000000u);
}

// Warp-synchronous exact top-K select + softmax weights over L scores in smem.
// sp: this warp's row of L scores. hb: this warp's 256-bin hist. idxl: this warp's
// compact index list (ascending). On exit sp[j] holds exp(s_j - vmax) for selected
// (ties -> lowest index first), 0 otherwise. Returns sum of selected exps.
template<int L, int KS>
__device__ __forceinline__ float warp_topk(float* sp, unsigned* hb,
                                           unsigned short* idxl, float vmax, int lane){
    const unsigned FULL = 0xffffffffu;
    unsigned prefix = 0; int need = KS;
    #pragma unroll
    for (int p = 3; p >= 0; p--){
        const int shift = p * 8;
        const unsigned maskhi = (p == 3) ? 0u : (0xffffffffu << (shift + 8));
        #pragma unroll
        for (int i = lane; i < 256; i += 32) hb[i] = 0;
        __syncwarp();
        for (int g = 0; g < L/32; g++){
            unsigned key = fkey(sp[g*32 + lane]);
            if ((key & maskhi) == prefix) atomicAdd(&hb[(key >> shift) & 255u], 1u);
        }
        __syncwarp();
        unsigned c[8]; unsigned tot = 0;
        #pragma unroll
        for (int i = 0; i < 8; i++){ c[i] = hb[lane*8 + i]; tot += c[i]; }
        // inclusive suffix-sum of lane totals
        unsigned run = tot;
        #pragma unroll
        for (int off = 1; off < 32; off <<= 1){
            unsigned v = __shfl_down_sync(FULL, run, off);
            if (lane + off < 32) run += v;
        }
        unsigned above = run - tot;   // sum over lanes > lane
        unsigned gtv = above, pack = 0;
        #pragma unroll
        for (int i = 7; i >= 0; i--){
            unsigned ge = gtv + c[i];
            if ((int)ge >= need && (int)gtv < need)
                pack = 0x80000000u | ((unsigned)(lane*8 + i) << 12) | gtv;
            gtv = ge;
        }
        #pragma unroll
        for (int off = 16; off; off >>= 1)
            pack = max(pack, __shfl_xor_sync(FULL, pack, off));
        unsigned bin = (pack >> 12) & 255u;
        need = need - (int)(pack & 0xFFFu);
        prefix |= bin << shift;
        __syncwarp();
    }
    const unsigned thr = prefix;
    int tieacc = 0, nsel = 0; float lsum = 0.f;
    for (int g = 0; g < L/32; g++){
        int j = g*32 + lane;
        float v = sp[j];
        unsigned key = fkey(v);
        bool eq = (key == thr);
        unsigned eqm = __ballot_sync(FULL, eq);
        bool sel = (key > thr) || (eq && (tieacc + __popc(eqm & ((1u<<lane) - 1u))) < need);
        tieacc += __popc(eqm);
        float e = sel ? __expf(v - vmax) : 0.f;
        sp[j] = e; lsum += e;
        unsigned sm = __ballot_sync(FULL, sel);
        if (sel) idxl[nsel + __popc(sm & ((1u<<lane) - 1u))] = (unsigned short)j;
        nsel += __popc(sm);
    }
    #pragma unroll
    for (int off = 16; off; off >>= 1) lsum += __shfl_xor_sync(FULL, lsum, off);
    return lsum;
}

// ---------------- kernel 1: qkv lora low = x @ qkv_A^T  (B,N,3,8) ----------------
__global__ void k_qkv_low(const float* __restrict__ x, const float* __restrict__ qkvA){
    const int row = blockIdx.x;
    const int tid = threadIdx.x;
    __shared__ float xs[Cc];
    for (int i = tid; i < Cc; i += NT) xs[i] = x[row*Cc + i];
    __syncthreads();
    const int warp = tid >> 5, lane = tid & 31;
    for (int o = warp; o < 24; o += 8){
        const float* a = &qkvA[o*Cc];
        float p = 0.f;
        for (int i = lane; i < Cc; i += 32) p += xs[i] * a[i];
        #pragma unroll
        for (int off = 16; off; off >>= 1) p += __shfl_xor_sync(0xffffffffu, p, off);
        if (lane == 0) g_qkvlow[row*24 + o] = p;
    }
}

// ---------------- shared SGEMM mainloop: out[m,n] = sum_k A[m,k]*W[n,k] ----------------
#define SGEMM_MAIN(Aptr, Wptr, KDIM)                                              \
    __shared__ __align__(16) float As[16*64];                                      \
    __shared__ __align__(16) float Ws[16*64];                                      \
    float acc[4][4];                                                               \
    _Pragma("unroll") for (int i_ = 0; i_ < 4; i_++)                               \
    _Pragma("unroll") for (int j_ = 0; j_ < 4; j_++) acc[i_][j_] = 0.f;            \
    const int tid = threadIdx.x;                                                   \
    const int ty = tid >> 4, tx = tid & 15;                                        \
    const int lr = tid >> 2, lk = (tid & 3) * 4;                                   \
    const int row0 = blockIdx.y * 64, col0 = blockIdx.x * 64;                      \
    for (int kt = 0; kt < KDIM; kt += 16){                                         \
        float4 a4 = *(const float4*)&Aptr[(row0 + lr)*KDIM + kt + lk];             \
        float4 w4 = *(const float4*)&Wptr[(col0 + lr)*KDIM + kt + lk];             \
        __syncthreads();                                                           \
        As[(lk+0)*64 + lr] = a4.x; As[(lk+1)*64 + lr] = a4.y;                      \
        As[(lk+2)*64 + lr] = a4.z; As[(lk+3)*64 + lr] = a4.w;                      \
        Ws[(lk+0)*64 + lr] = w4.x; Ws[(lk+1)*64 + lr] = w4.y;                      \
        Ws[(lk+2)*64 + lr] = w4.z; Ws[(lk+3)*64 + lr] = w4.w;                      \
        __syncthreads();                                                           \
        _Pragma("unroll")                                                          \
        for (int kk = 0; kk < 16; kk++){                                           \
            float4 ra = *(const float4*)&As[kk*64 + ty*4];                         \
            float4 rb = *(const float4*)&Ws[kk*64 + tx*4];                         \
            acc[0][0] += ra.x*rb.x; acc[0][1] += ra.x*rb.y;                        \
            acc[0][2] += ra.x*rb.z; acc[0][3] += ra.x*rb.w;                        \
            acc[1][0] += ra.y*rb.x; acc[1][1] += ra.y*rb.y;                        \
            acc[1][2] += ra.y*rb.z; acc[1][3] += ra.y*rb.w;                        \
            acc[2][0] += ra.z*rb.x; acc[2][1] += ra.z*rb.y;                        \
            acc[2][2] += ra.z*rb.z; acc[2][3] += ra.z*rb.w;                        \
            acc[3][0] += ra.w*rb.x; acc[3][1] += ra.w*rb.y;                        \
            acc[3][2] += ra.w*rb.z; acc[3][3] += ra.w*rb.w;                        \
        }                                                                          \
    }

// ---------------- kernel 2: QKV GEMM + bias + lora + scatter to (B,H,N,D) ----------------
__global__ void k_sgemm_qkv(const float* __restrict__ x, const float* __restrict__ W,
                            const float* __restrict__ bq, const float* __restrict__ qkvB){
    SGEMM_MAIN(x, W, Cc)
    const int g = col0 / Cc;
    #pragma unroll
    for (int ii = 0; ii < 4; ii++){
        const int m = row0 + ty*4 + ii;
        const int b = m / Nn, n = m % Nn;
        float lw[8];
        #pragma unroll
        for (int r = 0; r < 8; r++) lw[r] = g_qkvlow[m*24 + g*8 + r];
        #pragma unroll
        for (int jj = 0; jj < 4; jj++){
            const int j = col0 + tx*4 + jj;
            const int c = j - g*Cc;
            const float* bv = &qkvB[(g*Cc + c)*8];
            float lora = 0.f;
            #pragma unroll
            for (int r = 0; r < 8; r++) lora += lw[r] * bv[r];
            float val = acc[ii][jj] + bq[j] + 0.125f * lora;
            const int h = c >> 6, d = c & 63;
            const int dst = ((b*Hh + h)*Nn + n)*Dd + d;
            if (g == 0)      g_q[dst] = val * 0.125f;   // fold D^-0.5
            else if (g == 1) g_k[dst] = val;
            else             g_v[dst] = val;
        }
    }
}

// ---------------- kernel 3: ID_K activation + idv lora low ----------------
__global__ void k_id_small(const float* __restrict__ idt, const float* __restrict__ idkA,
                           const float* __restrict__ idvA, const float* __restrict__ Widk,
                           const float* __restrict__ bidk, const float* __restrict__ idkB){
    const int row = blockIdx.x;
    const int tid = threadIdx.x;
    __shared__ float xs[Cc];
    __shared__ float lk[8], dk[12];
    for (int i = tid; i < Cc; i += NT) xs[i] = idt[row*Cc + i];
    __syncthreads();
    const int warp = tid >> 5, lane = tid & 31;
    for (int o = warp; o < 28; o += 8){
        const float* a;
        if (o < 8)       a = &idkA[o*Cc];
        else if (o < 16) a = &idvA[(o - 8)*Cc];
        else             a = &Widk[(o - 16)*Cc];
        float p = 0.f;
        for (int i = lane; i < Cc; i += 32) p += xs[i] * a[i];
        #pragma unroll
        for (int off = 16; off; off >>= 1) p += __shfl_xor_sync(0xffffffffu, p, off);
        if (lane == 0){
            if (o < 8)       lk[o] = p;
            else if (o < 16) g_idvlow[row*8 + (o - 8)] = p;
            else             dk[o - 16] = p;
        }
    }
    __syncthreads();
    if (tid < 12){
        float lo = 0.f;
        #pragma unroll
        for (int r = 0; r < 8; r++) lo += lk[r] * idkB[tid*8 + r];
        float f = dk[tid] + bidk[tid] + 0.125f * lo;
        g_act[row*Hh + tid] = 1.f + tanhf(f);
    }
}

// ---------------- kernel 4: ID_V GEMM ----------------
__global__ void k_sgemm_idv(const float* __restrict__ idt, const float* __restrict__ W,
                            const float* __restrict__ bidv, const float* __restrict__ idvB){
    SGEMM_MAIN(idt, W, Cc)
    #pragma unroll
    for (int ii = 0; ii < 4; ii++){
        const int m = row0 + ty*4 + ii;
        float lw[8];
        #pragma unroll
        for (int r = 0; r < 8; r++) lw[r] = g_idvlow[m*8 + r];
        #pragma unroll
        for (int jj = 0; jj < 4; jj++){
            const int c = col0 + tx*4 + jj;
            const float* bv = &idvB[c*8];
            float lora = 0.f;
            #pragma unroll
            for (int r = 0; r < 8; r++) lora += lw[r] * bv[r];
            g_idv[m*Cc + c] = acc[ii][jj] + bidv[c] + 0.125f * lora;
        }
    }
}

// ---------------- kernel 5: apply identity mods -> k_m_id, v_m_id ----------------
__global__ void k_apply_id(float* __restrict__ kmid, float* __restrict__ vmid){
    const int idx = blockIdx.x * NT + threadIdx.x;
    const int d = idx & 63;
    int t = idx >> 6;
    const int m = t % NM; t /= NM;
    const int h = t % Hh; const int b = t / Hh;
    const int src = ((b*Hh + h)*Nn + m)*Dd + d;
    kmid[idx] = g_k[src] * g_act[(b*NM + m)*Hh + h];
    vmid[idx] = g_v[src] + g_idv[(b*NM + m)*Cc + h*Dd + d];
}

// ---------------- kernel 6: mem attention (8 query rows per block) ----------------
// smem: s[8*256] | kt[64*257] (reused as vsh[256*64]) | qs[512] | hist[8*256] | idxl[8*128]
#define SM_M_S    0
#define SM_M_KT   8192
#define SM_M_QS   74048       // 8192 + 65792 (KTP buffer = 64*257*4 = 65792)
#define SM_M_HIST 76096
#define SM_M_IDX  84288
#define SMEM_M_TOT 86336

__global__ void k_attn_m(const float* __restrict__ kmid, const float* __restrict__ vmid){
    extern __shared__ __align__(16) char smb[];
    float* s  = (float*)(smb + SM_M_S);
    float* kt = (float*)(smb + SM_M_KT);
    float* qs = (float*)(smb + SM_M_QS);
    unsigned* hist = (unsigned*)(smb + SM_M_HIST);
    unsigned short* idxl = (unsigned short*)(smb + SM_M_IDX);
    const int tid = threadIdx.x, lane = tid & 31, w = tid >> 5;
    const int qt = blockIdx.x & 31;
    const int bh = blockIdx.x >> 5;
    const int b = bh / Hh, h = bh % Hh;
    const int m0 = qt * 8;
    // load 8 q rows
    for (int i = tid; i < 512; i += NT){
        int r = i >> 6, d = i & 63;
        qs[i] = g_q[((size_t)bh*Nn + m0 + r)*Dd + d];
    }
    // load K (all 256 keys), transposed
    for (int idx = tid; idx < 256*16; idx += NT){
        int r = idx >> 4, c4 = idx & 15;
        float4 kv = *(const float4*)&kmid[((size_t)bh*NM + r)*Dd + c4*4];
        kt[(c4*4+0)*KTP + r] = kv.x;
        kt[(c4*4+1)*KTP + r] = kv.y;
        kt[(c4*4+2)*KTP + r] = kv.z;
        kt[(c4*4+3)*KTP + r] = kv.w;
    }
    __syncthreads();
    // scores: thread tid owns key tid, all 8 rows
    {
        float acc8[8];
        #pragma unroll
        for (int r = 0; r < 8; r++) acc8[r] = 0.f;
        const float4* qs4 = (const float4*)qs;
        #pragma unroll 4
        for (int i4 = 0; i4 < 16; i4++){
            float k0 = kt[(i4*4+0)*KTP + tid];
            float k1 = kt[(i4*4+1)*KTP + tid];
            float k2 = kt[(i4*4+2)*KTP + tid];
            float k3 = kt[(i4*4+3)*KTP + tid];
            #pragma unroll
            for (int r = 0; r < 8; r++){
                float4 q4 = qs4[r*16 + i4];
                acc8[r] += k0*q4.x + k1*q4.y + k2*q4.z + k3*q4.w;
            }
        }
        #pragma unroll
        for (int r = 0; r < 8; r++) s[r*NM + tid] = acc8[r];
    }
    __syncthreads();
    // per-warp: row w
    float* sp = s + w*NM;
    float lmax = -1e30f;
    for (int g = 0; g < NM/32; g++) lmax = fmaxf(lmax, sp[g*32 + lane]);
    #pragma unroll
    for (int off = 16; off; off >>= 1) lmax = fmaxf(lmax, __shfl_xor_sync(0xffffffffu, lmax, off));
    float Z = warp_topk<NM, KSEL_M>(sp, hist + w*256, idxl + w*KSEL_M, lmax, lane);
    float invZ = 1.f / Z;
    __syncthreads();
    // reload V (all 256 rows) into kt buffer, row-major
    float* vsh = kt;
    for (int idx = tid; idx < 256*16; idx += NT){
        int r = idx >> 4, c4 = idx & 15;
        *(float4*)&vsh[r*Dd + c4*4] = *(const float4*)&vmid[((size_t)bh*NM + r)*Dd + c4*4];
    }
    __syncthreads();
    float2 acc = {0.f, 0.f};
    const unsigned short* il = idxl + w*KSEL_M;
    for (int n = 0; n < KSEL_M; n++){
        int j = il[n];
        float wgt = sp[j];
        float2 v2 = ((const float2*)&vsh[j*Dd])[lane];
        acc.x += wgt*v2.x; acc.y += wgt*v2.y;
    }
    float2 o = {acc.x*invZ, acc.y*invZ};
    ((float2*)&g_xo[((size_t)b*Nn + m0 + w)*Cc + h*Dd])[lane] = o;
}

// ---------------- kernel 7: streaming attention (8 query rows per block) ----------------
// smem: s[8*2560] | kt[64*257] (reused as vsh) | qs[512] | hist[8*256] | idxl[8*640]
#define SM_S_S    0
#define SM_S_KT   81920
#define SM_S_QS   147712
#define SM_S_HIST 149760
#define SM_S_IDX  157952
#define SMEM_S_TOT 168192

__global__ void k_attn_s(const float* __restrict__ memk, const float* __restrict__ memv,
                         const float* __restrict__ vmid){
    extern __shared__ __align__(16) char smb[];
    float* s  = (float*)(smb + SM_S_S);
    float* kt = (float*)(smb + SM_S_KT);
    float* qs = (float*)(smb + SM_S_QS);
    unsigned* hist = (unsigned*)(smb + SM_S_HIST);
    unsigned short* idxl = (unsigned short*)(smb + SM_S_IDX);
    const int tid = threadIdx.x, lane = tid & 31, w = tid >> 5;
    const int qt = blockIdx.x & 127;
    const int bh = blockIdx.x >> 7;
    const int b = bh / Hh, h = bh % Hh;
    const int nq0 = NM + qt*8;
    for (int i = tid; i < 512; i += NT){
        int r = i >> 6, d = i & 63;
        qs[i] = g_q[((size_t)bh*Nn + nq0 + r)*Dd + d];
    }
    const float4* qs4 = (const float4*)qs;
    for (int ck = 0; ck < 10; ck++){
        __syncthreads();
        for (int idx = tid; idx < 256*16; idx += NT){
            int r = idx >> 4, c4 = idx & 15;
            int j = ck*256 + r;
            const float* kr = (j < MEMN) ? &memk[((size_t)bh*MEMN + j)*Dd]
                                         : &g_k[((size_t)bh*Nn + (j - MEMN))*Dd];
            float4 kv = *(const float4*)(kr + c4*4);
            kt[(c4*4+0)*KTP + r] = kv.x;
            kt[(c4*4+1)*KTP + r] = kv.y;
            kt[(c4*4+2)*KTP + r] = kv.z;
            kt[(c4*4+3)*KTP + r] = kv.w;
        }
        __syncthreads();
        float acc8[8];
        #pragma unroll
        for (int r = 0; r < 8; r++) acc8[r] = 0.f;
        #pragma unroll 4
        for (int i4 = 0; i4 < 16; i4++){
            float k0 = kt[(i4*4+0)*KTP + tid];
            float k1 = kt[(i4*4+1)*KTP + tid];
            float k2 = kt[(i4*4+2)*KTP + tid];
            float k3 = kt[(i4*4+3)*KTP + tid];
            #pragma unroll
            for (int r = 0; r < 8; r++){
                float4 q4 = qs4[r*16 + i4];
                acc8[r] += k0*q4.x + k1*q4.y + k2*q4.z + k3*q4.w;
            }
        }
        #pragma unroll
        for (int r = 0; r < 8; r++) s[r*LFULL + ck*256 + tid] = acc8[r];
    }
    __syncthreads();
    // per-warp select on row w
    float* sp = s + w*LFULL;
    float lmax = -1e30f;
    for (int g = 0; g < LFULL/32; g++) lmax = fmaxf(lmax, sp[g*32 + lane]);
    #pragma unroll
    for (int off = 16; off; off >>= 1) lmax = fmaxf(lmax, __shfl_xor_sync(0xffffffffu, lmax, off));
    float Z = warp_topk<LFULL, KSEL_S>(sp, hist + w*256, idxl + w*KSEL_S, lmax, lane);
    float invZ = 1.f / Z;
    // chunked sparse AV (indices ascending)
    float* vsh = kt;
    const unsigned short* il = idxl + w*KSEL_S;
    int n = 0;
    float2 acc = {0.f, 0.f};
    for (int ck = 0; ck < 10; ck++){
        __syncthreads();
        for (int idx = tid; idx < 256*16; idx += NT){
            int r = idx >> 4, c4 = idx & 15;
            int j = ck*256 + r;
            const float* vr;
            if (j < MEMN)            vr = &memv[((size_t)bh*MEMN + j)*Dd];
            else if (j < MEMN + NM)  vr = &vmid[((size_t)bh*NM + (j - MEMN))*Dd];
            else                     vr = &g_v[((size_t)bh*Nn + (j - MEMN))*Dd];
            *(float4*)&vsh[r*Dd + c4*4] = *(const float4*)(vr + c4*4);
        }
        __syncthreads();
        const int jend = (ck + 1)*256, jbase = ck*256;
        while (n < KSEL_S){
            int j = il[n];
            if (j >= jend) break;
            float wgt = sp[j];
            float2 v2 = ((const float2*)&vsh[(j - jbase)*Dd])[lane];
            acc.x += wgt*v2.x; acc.y += wgt*v2.y;
            n++;
        }
    }
    float2 o = {acc.x*invZ, acc.y*invZ};
    ((float2*)&g_xo[((size_t)b*Nn + nq0 + w)*Cc + h*Dd])[lane] = o;
}

// ---------------- kernel 8a: route softmax + weighted proj-lora lows ----------------
__global__ void k_route(const float* __restrict__ routeW, const float* __restrict__ projA){
    const int row = blockIdx.x;
    const int tid = threadIdx.x;
    __shared__ float xs[Cc];
    __shared__ float lg[4], pl[32], sm[4];
    for (int i = tid; i < Cc; i += NT) xs[i] = g_xo[row*Cc + i];
    __syncthreads();
    const int warp = tid >> 5, lane = tid & 31;
    for (int o = warp; o < 36; o += 8){
        const float* a = (o < 4) ? &routeW[o*Cc] : &projA[(o - 4)*Cc];
        float p = 0.f;
        for (int i = lane; i < Cc; i += 32) p += xs[i] * a[i];
        #pragma unroll
        for (int off = 16; off; off >>= 1) p += __shfl_xor_sync(0xffffffffu, p, off);
        if (lane == 0){
            if (o < 4) lg[o] = p;
            else       pl[o - 4] = p;
        }
    }
    __syncthreads();
    if (tid == 0){
        float mx = fmaxf(fmaxf(lg[0], lg[1]), fmaxf(lg[2], lg[3]));
        float e0 = __expf(lg[0]-mx), e1 = __expf(lg[1]-mx);
        float e2 = __expf(lg[2]-mx), e3 = __expf(lg[3]-mx);
        float si = 1.f / (e0 + e1 + e2 + e3);
        sm[0] = e0*si; sm[1] = e1*si; sm[2] = e2*si; sm[3] = e3*si;
    }
    __syncthreads();
    if (tid < 32) g_wplow[row*32 + tid] = sm[tid >> 3] * pl[tid] * 0.125f;
}

// ---------------- kernel 8b: output projection GEMM + MoE lora ----------------
__global__ void k_sgemm_proj(const float* __restrict__ W, const float* __restrict__ bp,
                             const float* __restrict__ projB, float* __restrict__ out){
    SGEMM_MAIN(g_xo, W, Cc)
    #pragma unroll
    for (int ii = 0; ii < 4; ii++){
        const int m = row0 + ty*4 + ii;
        float wl[32];
        #pragma unroll
        for (int t = 0; t < 32; t++) wl[t] = g_wplow[m*32 + t];
        #pragma unroll
        for (int jj = 0; jj < 4; jj++){
            const int c = col0 + tx*4 + jj;
            float lora = 0.f;
            #pragma unroll
            for (int e = 0; e < 4; e++){
                const float* bv = &projB[(e*Cc + c)*8];
                #pragma unroll
                for (int r = 0; r < 8; r++) lora += wl[e*8 + r] * bv[r];
            }
            out[m*Cc + c] = acc[ii][jj] + bp[c] + lora;
        }
    }
}

// ---------------- launch ----------------
extern "C" void kernel_launch(void* const* d_in, const int* in_sizes, int n_in,
                              void* d_out, int out_size){
    const float* x      = (const float*)d_in[0];
    const float* idt    = (const float*)d_in[1];
    const float* memk   = (const float*)d_in[2];
    const float* memv   = (const float*)d_in[3];
    const float* Wqkv   = (const float*)d_in[4];
    const float* bqkv   = (const float*)d_in[5];
    const float* qkvA   = (const float*)d_in[6];
    const float* qkvB   = (const float*)d_in[7];
    const float* Wproj  = (const float*)d_in[8];
    const float* bproj  = (const float*)d_in[9];
    const float* routeW = (const float*)d_in[10];
    const float* projA  = (const float*)d_in[11];
    const float* projB  = (const float*)d_in[12];
    const float* Widk   = (const float*)d_in[13];
    const float* bidk   = (const float*)d_in[14];
    const float* idkA   = (const float*)d_in[15];
    const float* idkB   = (const float*)d_in[16];
    const float* Widv   = (const float*)d_in[17];
    const float* bidv   = (const float*)d_in[18];
    const float* idvA   = (const float*)d_in[19];
    const float* idvB   = (const float*)d_in[20];

    float* out  = (float*)d_out;
    float* kmid = out + Bb*Nn*Cc;
    float* vmid = kmid + Bb*Hh*NM*Dd;

    static int init = 0;
    if (!init){
        cudaFuncSetAttribute(k_attn_m, cudaFuncAttributeMaxDynamicSharedMemorySize, SMEM_M_TOT);
        cudaFuncSetAttribute(k_attn_s, cudaFuncAttributeMaxDynamicSharedMemorySize, SMEM_S_TOT);
        init = 1;
    }

    k_qkv_low<<<Bb*Nn, NT>>>(x, qkvA);
    k_sgemm_qkv<<<dim3(36, 80), NT>>>(x, Wqkv, bqkv, qkvB);
    k_id_small<<<Bb*NM, NT>>>(idt, idkA, idvA, Widk, bidk, idkB);
    k_sgemm_idv<<<dim3(12, 16), NT>>>(idt, Widv, bidv, idvB);
    k_apply_id<<<(Bb*Hh*NM*Dd)/NT, NT>>>(kmid, vmid);
    k_attn_m<<<Bb*Hh*NM/8, NT, SMEM_M_TOT>>>(kmid, vmid);
    k_attn_s<<<Bb*Hh*NSd/8, NT, SMEM_S_TOT>>>(memk, memv, vmid);
    k_route<<<Bb*Nn, NT>>>(routeW, projA);
    k_sgemm_proj<<<dim3(12, 80), NT>>>(Wproj, bproj, projB, out);
}